// round 1
// baseline (speedup 1.0000x reference)
#include <cuda_runtime.h>

#define IN_F   4096
#define OUT_F  11008
#define TOKENS 8

#define THREADS 256
#define WARPS_PER_BLOCK (THREADS / 32)
#define GRID 148
#define SMEM_BYTES (TOKENS * IN_F * 4)   // 131072 B

__device__ float g_sumx[TOKENS];

// --- kernel 1: per-token row sums of x (tiny) --------------------------------
__global__ void dql_sumx(const float* __restrict__ x) {
    int t = threadIdx.y;     // 0..7
    int lane = threadIdx.x;  // 0..31
    float s = 0.f;
    for (int i = lane; i < IN_F; i += 32) s += x[t * IN_F + i];
    #pragma unroll
    for (int off = 16; off; off >>= 1) s += __shfl_xor_sync(0xffffffffu, s, off);
    if (lane == 0) g_sumx[t] = s;
}

// --- kernel 2: main streaming dequant-GEMV (8 tokens) ------------------------
__global__ __launch_bounds__(THREADS, 1)
void dql_main(const float* __restrict__ x,
              const float* __restrict__ W,
              const int*   __restrict__ Q,
              const float* __restrict__ scales,
              const float* __restrict__ zp,
              const float* __restrict__ bias,
              float*       __restrict__ out) {
    extern __shared__ float xs[];   // [TOKENS][IN_F]

    // Stage x into shared (128 KB), vectorized
    {
        const float4* x4 = (const float4*)x;
        float4* xs4 = (float4*)xs;
        #pragma unroll
        for (int i = threadIdx.x; i < TOKENS * IN_F / 4; i += THREADS)
            xs4[i] = x4[i];
    }
    __syncthreads();

    const int warp  = threadIdx.x >> 5;
    const int lane  = threadIdx.x & 31;
    const int gwarp = blockIdx.x * WARPS_PER_BLOCK + warp;
    const int nwarp = gridDim.x * WARPS_PER_BLOCK;
    const int NPAIR = OUT_F / 2;   // 5504

    const float4* xs4 = (const float4*)xs;

    for (int pair = gwarp; pair < NPAIR; pair += nwarp) {
        const int o0 = pair * 2;
        const int o1 = o0 + 1;
        const float s0 = scales[o0];
        const float s1 = scales[o1];

        const float4* w0 = (const float4*)(W + (size_t)o0 * IN_F);
        const float4* w1 = (const float4*)(W + (size_t)o1 * IN_F);
        const int4*   q0 = (const int4*)(Q + (size_t)o0 * IN_F);
        const int4*   q1 = (const int4*)(Q + (size_t)o1 * IN_F);

        float acc0[TOKENS], acc1[TOKENS];
        #pragma unroll
        for (int t = 0; t < TOKENS; t++) { acc0[t] = 0.f; acc1[t] = 0.f; }

        // 4096 cols / 4 per float4 / 32 lanes = 32 iterations
        #pragma unroll 2
        for (int c = lane; c < IN_F / 4; c += 32) {
            float4 wa = w0[c];
            float4 wb = w1[c];
            int4   qa = q0[c];
            int4   qb = q1[c];

            // effective weight: w + s*q  (zp folded out via sumx)
            float4 fa, fb;
            fa.x = fmaf(s0, (float)qa.x, wa.x);
            fa.y = fmaf(s0, (float)qa.y, wa.y);
            fa.z = fmaf(s0, (float)qa.z, wa.z);
            fa.w = fmaf(s0, (float)qa.w, wa.w);
            fb.x = fmaf(s1, (float)qb.x, wb.x);
            fb.y = fmaf(s1, (float)qb.y, wb.y);
            fb.z = fmaf(s1, (float)qb.z, wb.z);
            fb.w = fmaf(s1, (float)qb.w, wb.w);

            #pragma unroll
            for (int t = 0; t < TOKENS; t++) {
                float4 xv = xs4[t * (IN_F / 4) + c];
                acc0[t] = fmaf(fa.x, xv.x, acc0[t]);
                acc0[t] = fmaf(fa.y, xv.y, acc0[t]);
                acc0[t] = fmaf(fa.z, xv.z, acc0[t]);
                acc0[t] = fmaf(fa.w, xv.w, acc0[t]);
                acc1[t] = fmaf(fb.x, xv.x, acc1[t]);
                acc1[t] = fmaf(fb.y, xv.y, acc1[t]);
                acc1[t] = fmaf(fb.z, xv.z, acc1[t]);
                acc1[t] = fmaf(fb.w, xv.w, acc1[t]);
            }
        }

        // warp tree-reduce all 16 accumulators
        #pragma unroll
        for (int t = 0; t < TOKENS; t++) {
            #pragma unroll
            for (int off = 16; off; off >>= 1) {
                acc0[t] += __shfl_xor_sync(0xffffffffu, acc0[t], off);
                acc1[t] += __shfl_xor_sync(0xffffffffu, acc1[t], off);
            }
        }

        // lanes 0..7 write row o0, lanes 8..15 write row o1 (token = lane&7)
        if (lane < 16) {
            int t = lane & 7;
            if (lane < 8) {
                float c0 = -s0 * zp[o0];
                out[t * OUT_F + o0] = acc0[t] + c0 * g_sumx[t] + bias[o0];
            } else {
                float c1 = -s1 * zp[o1];
                out[t * OUT_F + o1] = acc1[t] + c1 * g_sumx[t] + bias[o1];
            }
        }
    }
}

extern "C" void kernel_launch(void* const* d_in, const int* in_sizes, int n_in,
                              void* d_out, int out_size) {
    const float* x      = (const float*)d_in[0];
    const float* W      = (const float*)d_in[1];
    const int*   Q      = (const int*)d_in[2];
    const float* scales = (const float*)d_in[3];
    const float* zp     = (const float*)d_in[4];
    const float* bias   = (const float*)d_in[5];
    float* out = (float*)d_out;

    cudaFuncSetAttribute(dql_main, cudaFuncAttributeMaxDynamicSharedMemorySize,
                         SMEM_BYTES);

    dql_sumx<<<1, dim3(32, TOKENS)>>>(x);
    dql_main<<<GRID, THREADS, SMEM_BYTES>>>(x, W, Q, scales, zp, bias, out);
}

// round 2
// speedup vs baseline: 1.2477x; 1.2477x over previous
#include <cuda_runtime.h>

#define IN_F   4096
#define OUT_F  11008
#define TOKENS 8

#define THREADS 512
#define WARPS_PER_BLOCK (THREADS / 32)
#define GRID 148
#define SMEM_BYTES (TOKENS * IN_F * 4)   // 131072 B

#define KCHUNK     1024                   // columns per work unit
#define KSPLIT     (IN_F / KCHUNK)        // 4
#define CHUNK_F4   (KCHUNK / 4)           // 256 float4 per chunk
#define NUNITS     ((OUT_F / 2) * KSPLIT) // 22016

__device__ float g_sumx[TOKENS];

// --- kernel 1: per-token row sums of x ---------------------------------------
__global__ void dql_sumx(const float* __restrict__ x) {
    int t = threadIdx.y;
    int lane = threadIdx.x;
    float s = 0.f;
    for (int i = lane; i < IN_F; i += 32) s += x[t * IN_F + i];
    #pragma unroll
    for (int off = 16; off; off >>= 1) s += __shfl_xor_sync(0xffffffffu, s, off);
    if (lane == 0) g_sumx[t] = s;
}

// --- kernel 2: init out = bias - s*zp*sumx -----------------------------------
__global__ void dql_init(const float* __restrict__ scales,
                         const float* __restrict__ zp,
                         const float* __restrict__ bias,
                         float* __restrict__ out) {
    int i = blockIdx.x * blockDim.x + threadIdx.x;
    if (i < TOKENS * OUT_F) {
        int t = i / OUT_F;
        int o = i - t * OUT_F;
        out[i] = fmaf(-scales[o] * zp[o], g_sumx[t], bias[o]);
    }
}

// --- kernel 3: main streaming dequant-GEMV -----------------------------------
__global__ __launch_bounds__(THREADS, 1)
void dql_main(const float* __restrict__ x,
              const float* __restrict__ W,
              const int*   __restrict__ Q,
              const float* __restrict__ scales,
              float*       __restrict__ out) {
    extern __shared__ float xs[];   // [TOKENS][IN_F]

    // Stage x into shared (128 KB), vectorized
    {
        const float4* x4 = (const float4*)x;
        float4* xs4w = (float4*)xs;
        #pragma unroll
        for (int i = threadIdx.x; i < TOKENS * IN_F / 4; i += THREADS)
            xs4w[i] = x4[i];
    }
    __syncthreads();

    const int warp  = threadIdx.x >> 5;
    const int lane  = threadIdx.x & 31;
    const int gwarp = blockIdx.x * WARPS_PER_BLOCK + warp;
    const int nwarp = GRID * WARPS_PER_BLOCK;   // 2368

    const float4* xs4 = (const float4*)xs;

    for (int u = gwarp; u < NUNITS; u += nwarp) {
        const int pair = u >> 2;       // row pair index
        const int kq   = u & 3;        // K chunk index
        const int o0   = pair << 1;
        const int o1   = o0 + 1;
        const float s0 = scales[o0];
        const float s1 = scales[o1];

        const float4* w0 = (const float4*)(W + (size_t)o0 * IN_F + kq * KCHUNK);
        const float4* w1 = (const float4*)(W + (size_t)o1 * IN_F + kq * KCHUNK);
        const int4*   q0 = (const int4*)(Q + (size_t)o0 * IN_F + kq * KCHUNK);
        const int4*   q1 = (const int4*)(Q + (size_t)o1 * IN_F + kq * KCHUNK);
        const float4* xb = xs4 + kq * CHUNK_F4;   // token stride = IN_F/4

        float acc0[TOKENS], acc1[TOKENS];
        #pragma unroll
        for (int t = 0; t < TOKENS; t++) { acc0[t] = 0.f; acc1[t] = 0.f; }

        // 256 float4 per chunk / 32 lanes = 8 iterations
        #pragma unroll 2
        for (int it = 0; it < CHUNK_F4 / 32; ++it) {
            const int c = it * 32 + lane;
            float4 wa = w0[c];
            float4 wb = w1[c];
            int4   qa = q0[c];
            int4   qb = q1[c];

            float4 fa, fb;
            fa.x = fmaf(s0, (float)qa.x, wa.x);
            fa.y = fmaf(s0, (float)qa.y, wa.y);
            fa.z = fmaf(s0, (float)qa.z, wa.z);
            fa.w = fmaf(s0, (float)qa.w, wa.w);
            fb.x = fmaf(s1, (float)qb.x, wb.x);
            fb.y = fmaf(s1, (float)qb.y, wb.y);
            fb.z = fmaf(s1, (float)qb.z, wb.z);
            fb.w = fmaf(s1, (float)qb.w, wb.w);

            #pragma unroll
            for (int t = 0; t < TOKENS; t++) {
                float4 xv = xb[t * (IN_F / 4) + c];
                acc0[t] = fmaf(fa.x, xv.x, acc0[t]);
                acc0[t] = fmaf(fa.y, xv.y, acc0[t]);
                acc0[t] = fmaf(fa.z, xv.z, acc0[t]);
                acc0[t] = fmaf(fa.w, xv.w, acc0[t]);
                acc1[t] = fmaf(fb.x, xv.x, acc1[t]);
                acc1[t] = fmaf(fb.y, xv.y, acc1[t]);
                acc1[t] = fmaf(fb.z, xv.z, acc1[t]);
                acc1[t] = fmaf(fb.w, xv.w, acc1[t]);
            }
        }

        // Segmented fold reduce: 16 values summed across 32 lanes in 31 shfls.
        // v[2t+r] = acc_r[t]; selector bit consumed at each level:
        //   idx bit0 = lane bit4, bit1 = lane bit3, bit2 = lane bit2, bit3 = lane bit1
        float v16[16];
        #pragma unroll
        for (int t = 0; t < TOKENS; t++) { v16[2*t] = acc0[t]; v16[2*t+1] = acc1[t]; }
        #pragma unroll
        for (int i = 0; i < 16; i++) v16[i] += __shfl_xor_sync(0xffffffffu, v16[i], 16);
        float v8[8];
        #pragma unroll
        for (int i = 0; i < 8; i++) v8[i] = (lane & 16) ? v16[2*i+1] : v16[2*i];
        #pragma unroll
        for (int i = 0; i < 8; i++) v8[i] += __shfl_xor_sync(0xffffffffu, v8[i], 8);
        float v4[4];
        #pragma unroll
        for (int i = 0; i < 4; i++) v4[i] = (lane & 8) ? v8[2*i+1] : v8[2*i];
        #pragma unroll
        for (int i = 0; i < 4; i++) v4[i] += __shfl_xor_sync(0xffffffffu, v4[i], 4);
        float v2[2];
        #pragma unroll
        for (int i = 0; i < 2; i++) v2[i] = (lane & 4) ? v4[2*i+1] : v4[2*i];
        #pragma unroll
        for (int i = 0; i < 2; i++) v2[i] += __shfl_xor_sync(0xffffffffu, v2[i], 2);
        float v1 = (lane & 2) ? v2[1] : v2[0];
        v1 += __shfl_xor_sync(0xffffffffu, v1, 1);

        if (!(lane & 1)) {
            int r = (lane >> 4) & 1;
            int t = ((lane >> 3) & 1) | (((lane >> 2) & 1) << 1) | (((lane >> 1) & 1) << 2);
            atomicAdd(out + t * OUT_F + o0 + r, v1);
        }
    }
}

extern "C" void kernel_launch(void* const* d_in, const int* in_sizes, int n_in,
                              void* d_out, int out_size) {
    const float* x      = (const float*)d_in[0];
    const float* W      = (const float*)d_in[1];
    const int*   Q      = (const int*)d_in[2];
    const float* scales = (const float*)d_in[3];
    const float* zp     = (const float*)d_in[4];
    const float* bias   = (const float*)d_in[5];
    float* out = (float*)d_out;

    cudaFuncSetAttribute(dql_main, cudaFuncAttributeMaxDynamicSharedMemorySize,
                         SMEM_BYTES);

    dql_sumx<<<1, dim3(32, TOKENS)>>>(x);
    dql_init<<<(TOKENS * OUT_F + 255) / 256, 256>>>(scales, zp, bias, out);
    dql_main<<<GRID, THREADS, SMEM_BYTES>>>(x, W, Q, scales, out);
}

// round 5
// speedup vs baseline: 1.2921x; 1.0356x over previous
#include <cuda_runtime.h>

#define IN_F   4096
#define OUT_F  11008
#define TOKENS 8

#define THREADS 512
#define WARPS_PER_BLOCK (THREADS / 32)
#define GRID 148
#define SMEM_BYTES (TOKENS * IN_F * 4)    // 131072 B x staging

#define KCHUNK     1024                   // columns per work unit
#define KSPLIT     (IN_F / KCHUNK)        // 4
#define CHUNK_F4   (KCHUNK / 4)           // 256 float4 per chunk
#define NUNITS     ((OUT_F / 2) * KSPLIT) // 22016

#define ZERO_BLOCKS ((TOKENS * OUT_F) / 256)   // 344 exactly
#define PRE_GRID    (ZERO_BLOCKS + TOKENS)     // 352

__device__ float g_sumx[TOKENS];

// --- kernel 1: zero out + per-token row sums of x (one parallel launch) ------
__global__ void dql_pre(const float* __restrict__ x, float* __restrict__ out) {
    int b = blockIdx.x;
    if (b < ZERO_BLOCKS) {
        out[b * 256 + threadIdx.x] = 0.f;
    } else {
        // block (b - ZERO_BLOCKS) reduces token t's row
        __shared__ float red[8];
        int t = b - ZERO_BLOCKS;
        int tid = threadIdx.x;
        float s = 0.f;
        for (int i = tid; i < IN_F; i += 256) s += x[t * IN_F + i];
        #pragma unroll
        for (int off = 16; off; off >>= 1) s += __shfl_xor_sync(0xffffffffu, s, off);
        if ((tid & 31) == 0) red[tid >> 5] = s;
        __syncthreads();
        if (tid < 8) {
            float v = red[tid];
            #pragma unroll
            for (int off = 4; off; off >>= 1) v += __shfl_xor_sync(0xffu, v, off);
            if (tid == 0) g_sumx[t] = v;
        }
    }
}

// --- kernel 2: main streaming dequant-GEMV -----------------------------------
__global__ __launch_bounds__(THREADS, 1)
void dql_main(const float* __restrict__ x,
              const float* __restrict__ W,
              const int*   __restrict__ Q,
              const float* __restrict__ scales,
              const float* __restrict__ zp,
              const float* __restrict__ bias,
              float*       __restrict__ out) {
    extern __shared__ float xs[];   // [TOKENS][IN_F]

    // Stage x into shared (128 KB), vectorized
    {
        const float4* x4 = (const float4*)x;
        float4* xs4w = (float4*)xs;
        #pragma unroll
        for (int i = threadIdx.x; i < TOKENS * IN_F / 4; i += THREADS)
            xs4w[i] = x4[i];
    }
    __syncthreads();

    const int warp  = threadIdx.x >> 5;
    const int lane  = threadIdx.x & 31;
    const int gwarp = blockIdx.x * WARPS_PER_BLOCK + warp;
    const int nwarp = GRID * WARPS_PER_BLOCK;   // 2368

    const float4* xs4 = (const float4*)xs;

    for (int u = gwarp; u < NUNITS; u += nwarp) {
        const int pair = u >> 2;       // row pair index
        const int kq   = u & 3;        // K chunk index
        const int o0   = pair << 1;
        const int o1   = o0 + 1;
        const float s0 = scales[o0];
        const float s1 = scales[o1];

        const float4* w0 = (const float4*)(W + (size_t)o0 * IN_F + kq * KCHUNK);
        const float4* w1 = (const float4*)(W + (size_t)o1 * IN_F + kq * KCHUNK);
        const int4*   q0 = (const int4*)(Q + (size_t)o0 * IN_F + kq * KCHUNK);
        const int4*   q1 = (const int4*)(Q + (size_t)o1 * IN_F + kq * KCHUNK);
        const float4* xb = xs4 + kq * CHUNK_F4;   // token stride = IN_F/4

        float acc0[TOKENS], acc1[TOKENS];
        #pragma unroll
        for (int t = 0; t < TOKENS; t++) { acc0[t] = 0.f; acc1[t] = 0.f; }

        // 256 float4 per chunk / 32 lanes = 8 iterations; unroll 4 for MLP
        #pragma unroll 4
        for (int it = 0; it < CHUNK_F4 / 32; ++it) {
            const int c = it * 32 + lane;
            float4 wa = w0[c];
            float4 wb = w1[c];
            int4   qa = q0[c];
            int4   qb = q1[c];

            float4 fa, fb;
            fa.x = fmaf(s0, (float)qa.x, wa.x);
            fa.y = fmaf(s0, (float)qa.y, wa.y);
            fa.z = fmaf(s0, (float)qa.z, wa.z);
            fa.w = fmaf(s0, (float)qa.w, wa.w);
            fb.x = fmaf(s1, (float)qb.x, wb.x);
            fb.y = fmaf(s1, (float)qb.y, wb.y);
            fb.z = fmaf(s1, (float)qb.z, wb.z);
            fb.w = fmaf(s1, (float)qb.w, wb.w);

            #pragma unroll
            for (int t = 0; t < TOKENS; t++) {
                float4 xv = xb[t * (IN_F / 4) + c];
                acc0[t] = fmaf(fa.x, xv.x, acc0[t]);
                acc0[t] = fmaf(fa.y, xv.y, acc0[t]);
                acc0[t] = fmaf(fa.z, xv.z, acc0[t]);
                acc0[t] = fmaf(fa.w, xv.w, acc0[t]);
                acc1[t] = fmaf(fb.x, xv.x, acc1[t]);
                acc1[t] = fmaf(fb.y, xv.y, acc1[t]);
                acc1[t] = fmaf(fb.z, xv.z, acc1[t]);
                acc1[t] = fmaf(fb.w, xv.w, acc1[t]);
            }
        }

        // Segmented fold reduce: 16 values summed across 32 lanes in 31 shfls.
        float v16[16];
        #pragma unroll
        for (int t = 0; t < TOKENS; t++) { v16[2*t] = acc0[t]; v16[2*t+1] = acc1[t]; }
        #pragma unroll
        for (int i = 0; i < 16; i++) v16[i] += __shfl_xor_sync(0xffffffffu, v16[i], 16);
        float v8[8];
        #pragma unroll
        for (int i = 0; i < 8; i++) v8[i] = (lane & 16) ? v16[2*i+1] : v16[2*i];
        #pragma unroll
        for (int i = 0; i < 8; i++) v8[i] += __shfl_xor_sync(0xffffffffu, v8[i], 8);
        float v4[4];
        #pragma unroll
        for (int i = 0; i < 4; i++) v4[i] = (lane & 8) ? v8[2*i+1] : v8[2*i];
        #pragma unroll
        for (int i = 0; i < 4; i++) v4[i] += __shfl_xor_sync(0xffffffffu, v4[i], 4);
        float v2[2];
        #pragma unroll
        for (int i = 0; i < 2; i++) v2[i] = (lane & 4) ? v4[2*i+1] : v4[2*i];
        #pragma unroll
        for (int i = 0; i < 2; i++) v2[i] += __shfl_xor_sync(0xffffffffu, v2[i], 2);
        float v1 = (lane & 2) ? v2[1] : v2[0];
        v1 += __shfl_xor_sync(0xffffffffu, v1, 1);

        if (!(lane & 1)) {
            int r = (lane >> 4) & 1;
            int t = ((lane >> 3) & 1) | (((lane >> 2) & 1) << 1) | (((lane >> 1) & 1) << 2);
            int o = o0 + r;
            if (kq == 0) {
                float sr = r ? s1 : s0;
                v1 += fmaf(-sr * zp[o], __ldg(&g_sumx[t]), bias[o]);
            }
            atomicAdd(out + t * OUT_F + o, v1);
        }
    }
}

extern "C" void kernel_launch(void* const* d_in, const int* in_sizes, int n_in,
                              void* d_out, int out_size) {
    const float* x      = (const float*)d_in[0];
    const float* W      = (const float*)d_in[1];
    const int*   Q      = (const int*)d_in[2];
    const float* scales = (const float*)d_in[3];
    const float* zp     = (const float*)d_in[4];
    const float* bias   = (const float*)d_in[5];
    float* out = (float*)d_out;

    cudaFuncSetAttribute(dql_main, cudaFuncAttributeMaxDynamicSharedMemorySize,
                         SMEM_BYTES);

    dql_pre<<<PRE_GRID, 256>>>(x, out);
    dql_main<<<GRID, THREADS, SMEM_BYTES>>>(x, W, Q, scales, zp, bias, out);
}